// round 9
// baseline (speedup 1.0000x reference)
#include <cuda_runtime.h>
#include <cuda_bf16.h>
#include <math.h>
#include <stdint.h>

#define NVAR 30000
#define NCLS 60000
#define DIM 256
#define NHEAD 8

// ---------------- scratch layout (float units) ----------------
#define OFF_NUMVP  0ull            // 30000*256
#define OFF_NUMVN  7680000ull      // 30000*256
#define OFF_NUMCP  15360000ull     // 60000*256
#define OFF_NUMCN  30720000ull     // 60000*256
#define OFF_DENVP  46080000ull     // 30000*8
#define OFF_DENVN  46320000ull
#define OFF_DENCP  46560000ull     // 60000*8
#define OFF_DENCN  47040000ull
#define OFF_V1     47520000ull     // 30000*256 fp32
#define OFF_C1     55200000ull     // 60000*256 fp32
#define OFF_TMP    70560000ull     // 60000*256 fp32
#define OFF_B768   85920000ull     // 1024 floats
#define OFF_BF     85921024ull     // bf16 area below (bf16-element offsets)
#define B_VBF   0ull               // 30000*256
#define B_CBF   7680000ull         // 60000*256
#define B_PVB   23040000ull        // 30000*768  [q|k|v] bf16
#define B_PCB   46080000ull        // 60000*768
#define B_V1B   92160000ull        // 30000*256
#define B_C1B   99840000ull        // 60000*256
#define B_HID   115200000ull       // 60000*256
#define B_WQKV  130560000ull       // 256*768
#define B_FFNW  130756608ull       // 4*65536
#define SCRATCH_TOTAL 151430400ull

__device__ float g_scratch[SCRATCH_TOTAL];

// ---------------- helpers ----------------
__device__ __forceinline__ void ldsm_x4(uint32_t* r, uint32_t saddr) {
    asm volatile("ldmatrix.sync.aligned.m8n8.x4.shared.b16 {%0,%1,%2,%3}, [%4];"
                 : "=r"(r[0]), "=r"(r[1]), "=r"(r[2]), "=r"(r[3]) : "r"(saddr));
}
__device__ __forceinline__ void ldsm_x4_trans(uint32_t* r, uint32_t saddr) {
    asm volatile("ldmatrix.sync.aligned.m8n8.x4.trans.shared.b16 {%0,%1,%2,%3}, [%4];"
                 : "=r"(r[0]), "=r"(r[1]), "=r"(r[2]), "=r"(r[3]) : "r"(saddr));
}
__device__ __forceinline__ void mma_bf16(float* d, const uint32_t* a, const uint32_t* b) {
    asm volatile(
        "mma.sync.aligned.m16n8k16.row.col.f32.bf16.bf16.f32 "
        "{%0,%1,%2,%3}, {%4,%5,%6,%7}, {%8,%9}, {%0,%1,%2,%3};"
        : "+f"(d[0]), "+f"(d[1]), "+f"(d[2]), "+f"(d[3])
        : "r"(a[0]), "r"(a[1]), "r"(a[2]), "r"(a[3]),
          "r"(b[0]), "r"(b[1]));
}
__device__ __forceinline__ void red_add_v4(float* addr, float4 v) {
    asm volatile("red.global.add.v4.f32 [%0], {%1,%2,%3,%4};"
                 :: "l"(addr), "f"(v.x), "f"(v.y), "f"(v.z), "f"(v.w) : "memory");
}

// ---------------- conversion kernels ----------------
__global__ void cvt_f2b4(const float* __restrict__ s, __nv_bfloat16* __restrict__ d, int n4) {
    int i = blockIdx.x * blockDim.x + threadIdx.x;
    if (i >= n4) return;
    float4 t = ((const float4*)s)[i];
    __nv_bfloat162 lo = __float22bfloat162_rn(make_float2(t.x, t.y));
    __nv_bfloat162 hi = __float22bfloat162_rn(make_float2(t.z, t.w));
    ((uint2*)d)[i] = make_uint2(*(uint32_t*)&lo, *(uint32_t*)&hi);
}
__global__ void cvt_w4(const float* __restrict__ w1, const float* __restrict__ w2,
                       const float* __restrict__ w3, const float* __restrict__ w4,
                       __nv_bfloat16* __restrict__ dst) {
    int i = blockIdx.x * blockDim.x + threadIdx.x;
    if (i >= 65536) return;
    int which = i >> 14;
    int j = i & 16383;
    const float* src = (which == 0) ? w1 : (which == 1) ? w2 : (which == 2) ? w3 : w4;
    float4 t = ((const float4*)src)[j];
    __nv_bfloat162 lo = __float22bfloat162_rn(make_float2(t.x, t.y));
    __nv_bfloat162 hi = __float22bfloat162_rn(make_float2(t.z, t.w));
    ((uint2*)(dst + (size_t)which * 65536))[j] = make_uint2(*(uint32_t*)&lo, *(uint32_t*)&hi);
}
__global__ void build_wqkv(const float* __restrict__ Wq, const float* __restrict__ Wkv,
                           __nv_bfloat16* __restrict__ dst) {
    int i = blockIdx.x * blockDim.x + threadIdx.x;
    if (i >= 256 * 768) return;
    int k = i / 768, j = i % 768;
    float val = (j < 256) ? Wq[k * 256 + j] : Wkv[k * 512 + (j - 256)];
    dst[i] = __float2bfloat16(val);
}
__global__ void build_bias768(const float* __restrict__ bq, const float* __restrict__ bkv,
                              float* __restrict__ dst) {
    int j = blockIdx.x * blockDim.x + threadIdx.x;
    if (j < 768) dst[j] = (j < 256) ? bq[j] : bkv[j - 256];
}

// ---------------- bf16 tensor-core GEMM, 128x128 tile, double-buffered ----------------
#define BM 128
#define BN 128
#define BK 32
#define ASTR 40
#define BSTR 136

__global__ __launch_bounds__(256, 2) void tgemm(
    const __nv_bfloat16* __restrict__ A, int lda,
    const __nv_bfloat16* __restrict__ W,
    const float* __restrict__ bias,
    float* __restrict__ C,
    __nv_bfloat16* __restrict__ Cb, int cbs,
    int N, int M, int gelu)
{
    __shared__ __nv_bfloat16 As[2][BM * ASTR];
    __shared__ __nv_bfloat16 Ws[2][BK * BSTR];

    int tid = threadIdx.x;
    int lane = tid & 31;
    int warp = tid >> 5;
    int wm = (warp & 3) * 32;
    int wn = (warp >> 2) * 64;
    int bm = blockIdx.y * BM;
    int bn = blockIdx.x * BN;

    uint32_t as_base = (uint32_t)__cvta_generic_to_shared(&As[0][0]);
    uint32_t ws_base = (uint32_t)__cvta_generic_to_shared(&Ws[0][0]);
    const uint32_t as_sz = BM * ASTR * 2;
    const uint32_t ws_sz = BK * BSTR * 2;

    int a_row[2], a_col[2], w_row[2], w_col[2];
    #pragma unroll
    for (int i = 0; i < 2; i++) {
        int g = tid + i * 256;
        a_row[i] = (tid * 2 + i) >> 2;
        a_col[i] = ((tid * 2 + i) & 3) * 8;
        w_row[i] = g >> 4;
        w_col[i] = (g & 15) * 8;
    }

    uint4 pa[2], pb[2];
    const uint4 zero4 = make_uint4(0, 0, 0, 0);

    float acc[2][8][4];
    #pragma unroll
    for (int mt = 0; mt < 2; mt++)
        #pragma unroll
        for (int nt = 0; nt < 8; nt++)
            #pragma unroll
            for (int i = 0; i < 4; i++) acc[mt][nt][i] = 0.0f;

    int a_r = lane & 15;
    int a_c = (lane >> 4) * 8;

    #pragma unroll
    for (int i = 0; i < 2; i++) {
        int gr = bm + a_row[i];
        pa[i] = (gr < N) ? *(const uint4*)&A[(size_t)gr * lda + a_col[i]] : zero4;
        pb[i] = *(const uint4*)&W[(size_t)w_row[i] * M + bn + w_col[i]];
    }
    #pragma unroll
    for (int i = 0; i < 2; i++) {
        *(uint4*)&As[0][a_row[i] * ASTR + a_col[i]] = pa[i];
        *(uint4*)&Ws[0][w_row[i] * BSTR + w_col[i]] = pb[i];
    }
    __syncthreads();

    for (int s = 0; s < 8; s++) {
        int cur = s & 1, nxt = cur ^ 1;
        if (s < 7) {
            int k0 = (s + 1) * BK;
            #pragma unroll
            for (int i = 0; i < 2; i++) {
                int gr = bm + a_row[i];
                pa[i] = (gr < N) ? *(const uint4*)&A[(size_t)gr * lda + k0 + a_col[i]] : zero4;
                pb[i] = *(const uint4*)&W[(size_t)(k0 + w_row[i]) * M + bn + w_col[i]];
            }
        }

        uint32_t asb = as_base + cur * as_sz;
        uint32_t wsb = ws_base + cur * ws_sz;
        #pragma unroll
        for (int ks = 0; ks < 2; ks++) {
            int kb = ks * 16;
            uint32_t af[2][4], bf[4][4];
            #pragma unroll
            for (int mt = 0; mt < 2; mt++) {
                int row = wm + mt * 16 + a_r;
                int col = kb + a_c;
                ldsm_x4(af[mt], asb + (uint32_t)(row * ASTR + col) * 2);
            }
            #pragma unroll
            for (int p = 0; p < 4; p++) {
                int row = kb + (lane & 15);
                int col = wn + p * 16 + (lane >> 4) * 8;
                ldsm_x4_trans(bf[p], wsb + (uint32_t)(row * BSTR + col) * 2);
            }
            #pragma unroll
            for (int mt = 0; mt < 2; mt++)
                #pragma unroll
                for (int nt = 0; nt < 8; nt++)
                    mma_bf16(acc[mt][nt], af[mt], &bf[nt >> 1][(nt & 1) * 2]);
        }

        if (s < 7) {
            #pragma unroll
            for (int i = 0; i < 2; i++) {
                *(uint4*)&As[nxt][a_row[i] * ASTR + a_col[i]] = pa[i];
                *(uint4*)&Ws[nxt][w_row[i] * BSTR + w_col[i]] = pb[i];
            }
            __syncthreads();
        }
    }

    #pragma unroll
    for (int mt = 0; mt < 2; mt++) {
        int r0 = bm + wm + mt * 16 + (lane >> 2);
        #pragma unroll
        for (int nt = 0; nt < 8; nt++) {
            int cb = bn + wn + nt * 8 + (lane & 3) * 2;
            float b0 = bias[cb], b1 = bias[cb + 1];
            float2 lo = make_float2(acc[mt][nt][0] + b0, acc[mt][nt][1] + b1);
            float2 hi = make_float2(acc[mt][nt][2] + b0, acc[mt][nt][3] + b1);
            if (gelu) {
                lo.x = 0.5f * lo.x * (1.0f + erff(lo.x * 0.70710678118654752f));
                lo.y = 0.5f * lo.y * (1.0f + erff(lo.y * 0.70710678118654752f));
                hi.x = 0.5f * hi.x * (1.0f + erff(hi.x * 0.70710678118654752f));
                hi.y = 0.5f * hi.y * (1.0f + erff(hi.y * 0.70710678118654752f));
            }
            if (C) {
                if (r0 < N)     *(float2*)&C[(size_t)r0 * M + cb] = lo;
                if (r0 + 8 < N) *(float2*)&C[(size_t)(r0 + 8) * M + cb] = hi;
            }
            if (Cb) {
                __nv_bfloat162 blo = __float22bfloat162_rn(lo);
                __nv_bfloat162 bhi = __float22bfloat162_rn(hi);
                if (r0 < N)     *(__nv_bfloat162*)&Cb[(size_t)r0 * cbs + cb] = blo;
                if (r0 + 8 < N) *(__nv_bfloat162*)&Cb[(size_t)(r0 + 8) * cbs + cb] = bhi;
            }
        }
    }
}

// ---------------- merged edge attention: all 4 passes, one warp per edge ----------------
// pass = gw/E: 0 v-side/pos, 1 c-side/pos, 2 v-side/neg, 3 c-side/neg
// lane owns dims [lane*8, lane*8+8); head = lane>>2 for both score and value.
__global__ void edge_attn_all(
    const __nv_bfloat16* __restrict__ pvb,
    const __nv_bfloat16* __restrict__ pcb,
    const int* __restrict__ adj_pos, const int* __restrict__ adj_neg, int E,
    float* __restrict__ numVp, float* __restrict__ numCp,
    float* __restrict__ numVn, float* __restrict__ numCn,
    float* __restrict__ denVp, float* __restrict__ denCp,
    float* __restrict__ denVn, float* __restrict__ denCn)
{
    int gw = (int)(((size_t)blockIdx.x * blockDim.x + threadIdx.x) >> 5);
    int lane = threadIdx.x & 31;
    if (gw >= 4 * E) return;
    int pass = gw / E;
    int e = gw - pass * E;

    const int* adj = (pass & 2) ? adj_neg : adj_pos;
    int vside = !(pass & 1);
    int s, t;
    const __nv_bfloat16 *Qb, *KVb;
    float *num, *den;
    if (vside) {
        s = adj[E + e]; t = adj[e];
        Qb = pvb; KVb = pcb;
        num = (pass & 2) ? numVn : numVp;
        den = (pass & 2) ? denVn : denVp;
    } else {
        s = adj[e]; t = adj[E + e];
        Qb = pcb; KVb = pvb;
        num = (pass & 2) ? numCn : numCp;
        den = (pass & 2) ? denCn : denCp;
    }

    uint4 qu = *(const uint4*)&Qb[(size_t)s * 768 + lane * 8];
    uint4 ku = *(const uint4*)&KVb[(size_t)t * 768 + 256 + lane * 8];
    float p = 0.0f;
    {
        const __nv_bfloat162* qp = (const __nv_bfloat162*)&qu;
        const __nv_bfloat162* kp = (const __nv_bfloat162*)&ku;
        #pragma unroll
        for (int i = 0; i < 4; i++) {
            float2 qf = __bfloat1622float2(qp[i]);
            float2 kf = __bfloat1622float2(kp[i]);
            p += qf.x * kf.x + qf.y * kf.y;
        }
    }
    p += __shfl_xor_sync(0xffffffffu, p, 1);
    p += __shfl_xor_sync(0xffffffffu, p, 2);
    float ew = __expf(p * 0.17677669529663687f);   // this lane's head = lane>>2

    if ((lane & 3) == 0)
        atomicAdd(&den[(size_t)s * NHEAD + (lane >> 2)], ew);

    uint4 vu = *(const uint4*)&KVb[(size_t)t * 768 + 512 + lane * 8];
    const __nv_bfloat162* vp = (const __nv_bfloat162*)&vu;
    float2 v0 = __bfloat1622float2(vp[0]);
    float2 v1_ = __bfloat1622float2(vp[1]);
    float2 v2 = __bfloat1622float2(vp[2]);
    float2 v3 = __bfloat1622float2(vp[3]);
    float* base = &num[(size_t)s * 256 + lane * 8];
    red_add_v4(base,     make_float4(ew * v0.x, ew * v0.y, ew * v1_.x, ew * v1_.y));
    red_add_v4(base + 4, make_float4(ew * v2.x, ew * v2.y, ew * v3.x, ew * v3.y));
}

// ---------------- y = LN(x + num_p/den_p + num_n/den_n), dual fp32+bf16 out ----------------
__global__ void ln_att(const float* __restrict__ x,
                       const float* __restrict__ np_, const float* __restrict__ dp,
                       const float* __restrict__ nn_, const float* __restrict__ dn,
                       const float* __restrict__ g, const float* __restrict__ b,
                       float* __restrict__ y, __nv_bfloat16* __restrict__ yb, int n)
{
    int row = blockIdx.x * (blockDim.x >> 5) + (threadIdx.x >> 5);
    int lane = threadIdx.x & 31;
    if (row >= n) return;
    float vals[8];
    float s = 0.0f;
    #pragma unroll
    for (int i = 0; i < 8; i++) {
        size_t idx = (size_t)row * 256 + i * 32 + lane;
        float a = x[idx];
        float dpi = dp[(size_t)row * NHEAD + i];
        float dni = dn[(size_t)row * NHEAD + i];
        if (dpi > 0.0f) a += np_[idx] / dpi;
        if (dni > 0.0f) a += nn_[idx] / dni;
        vals[i] = a;
        s += a;
    }
    #pragma unroll
    for (int o = 16; o > 0; o >>= 1) s += __shfl_xor_sync(0xffffffffu, s, o);
    float mean = s * (1.0f / 256.0f);
    float v2 = 0.0f;
    #pragma unroll
    for (int i = 0; i < 8; i++) { float d = vals[i] - mean; v2 += d * d; }
    #pragma unroll
    for (int o = 16; o > 0; o >>= 1) v2 += __shfl_xor_sync(0xffffffffu, v2, o);
    float rstd = rsqrtf(v2 * (1.0f / 256.0f) + 1e-5f);
    #pragma unroll
    for (int i = 0; i < 8; i++) {
        int cidx = i * 32 + lane;
        float out = (vals[i] - mean) * rstd * g[cidx] + b[cidx];
        y[(size_t)row * 256 + cidx] = out;
        yb[(size_t)row * 256 + cidx] = __float2bfloat16(out);
    }
}

// ---------------- y = LN(x + a) ----------------
__global__ void ln_add(const float* __restrict__ x, const float* __restrict__ a,
                       const float* __restrict__ g, const float* __restrict__ b,
                       float* __restrict__ y, int n)
{
    int row = blockIdx.x * (blockDim.x >> 5) + (threadIdx.x >> 5);
    int lane = threadIdx.x & 31;
    if (row >= n) return;
    float vals[8];
    float s = 0.0f;
    #pragma unroll
    for (int i = 0; i < 8; i++) {
        size_t idx = (size_t)row * 256 + i * 32 + lane;
        vals[i] = x[idx] + a[idx];
        s += vals[i];
    }
    #pragma unroll
    for (int o = 16; o > 0; o >>= 1) s += __shfl_xor_sync(0xffffffffu, s, o);
    float mean = s * (1.0f / 256.0f);
    float v2 = 0.0f;
    #pragma unroll
    for (int i = 0; i < 8; i++) { float d = vals[i] - mean; v2 += d * d; }
    #pragma unroll
    for (int o = 16; o > 0; o >>= 1) v2 += __shfl_xor_sync(0xffffffffu, v2, o);
    float rstd = rsqrtf(v2 * (1.0f / 256.0f) + 1e-5f);
    #pragma unroll
    for (int i = 0; i < 8; i++) {
        int cidx = i * 32 + lane;
        y[(size_t)row * 256 + cidx] = (vals[i] - mean) * rstd * g[cidx] + b[cidx];
    }
}

static inline void launch_gemm(const __nv_bfloat16* A, int lda, const __nv_bfloat16* W,
                               const float* bias, float* C,
                               __nv_bfloat16* Cb, int cbs,
                               int N, int M, int gelu) {
    dim3 grid(M / BN, (N + BM - 1) / BM);
    tgemm<<<grid, 256>>>(A, lda, W, bias, C, Cb, cbs, N, M, gelu);
}

extern "C" void kernel_launch(void* const* d_in, const int* in_sizes, int n_in,
                              void* d_out, int out_size)
{
    const float* v       = (const float*)d_in[0];
    const float* c       = (const float*)d_in[1];
    const int*   adj_pos = (const int*)d_in[2];
    const int*   adj_neg = (const int*)d_in[3];
    const float* Wq      = (const float*)d_in[4];
    const float* bq      = (const float*)d_in[5];
    const float* Wkv     = (const float*)d_in[6];
    const float* bkv     = (const float*)d_in[7];
    const float* fvw1    = (const float*)d_in[8];
    const float* fvb1    = (const float*)d_in[9];
    const float* fvw2    = (const float*)d_in[10];
    const float* fvb2    = (const float*)d_in[11];
    const float* fcw1    = (const float*)d_in[12];
    const float* fcb1    = (const float*)d_in[13];
    const float* fcw2    = (const float*)d_in[14];
    const float* fcb2    = (const float*)d_in[15];
    const float* lavg    = (const float*)d_in[16];
    const float* lavb    = (const float*)d_in[17];
    const float* lfvg    = (const float*)d_in[18];
    const float* lfvb    = (const float*)d_in[19];
    const float* lacg    = (const float*)d_in[20];
    const float* lacb    = (const float*)d_in[21];
    const float* lfcg    = (const float*)d_in[22];
    const float* lfcb    = (const float*)d_in[23];

    int E = in_sizes[2] / 2;

    float* buf;
    cudaGetSymbolAddress((void**)&buf, g_scratch);

    float* numVp = buf + OFF_NUMVP;
    float* numVn = buf + OFF_NUMVN;
    float* numCp = buf + OFF_NUMCP;
    float* numCn = buf + OFF_NUMCN;
    float* denVp = buf + OFF_DENVP;
    float* denVn = buf + OFF_DENVN;
    float* denCp = buf + OFF_DENCP;
    float* denCn = buf + OFF_DENCN;
    float* v1    = buf + OFF_V1;
    float* c1    = buf + OFF_C1;
    float* tmp   = buf + OFF_TMP;
    float* b768  = buf + OFF_B768;

    __nv_bfloat16* bfb   = (__nv_bfloat16*)(buf + OFF_BF);
    __nv_bfloat16* v_bf  = bfb + B_VBF;
    __nv_bfloat16* c_bf  = bfb + B_CBF;
    __nv_bfloat16* pvb   = bfb + B_PVB;
    __nv_bfloat16* pcb   = bfb + B_PCB;
    __nv_bfloat16* v1b   = bfb + B_V1B;
    __nv_bfloat16* c1b   = bfb + B_C1B;
    __nv_bfloat16* hidb  = bfb + B_HID;
    __nv_bfloat16* wqkvb = bfb + B_WQKV;
    __nv_bfloat16* ffnw  = bfb + B_FFNW;
    __nv_bfloat16* fvw1b = ffnw;
    __nv_bfloat16* fvw2b = ffnw + 65536;
    __nv_bfloat16* fcw1b = ffnw + 131072;
    __nv_bfloat16* fcw2b = ffnw + 196608;

    float* out_v = (float*)d_out;
    float* out_c = out_v + (size_t)NVAR * DIM;

    // ---- conversions ----
    cvt_f2b4<<<(NVAR * 64 + 255) / 256, 256>>>(v, v_bf, NVAR * 64);
    cvt_f2b4<<<(NCLS * 64 + 255) / 256, 256>>>(c, c_bf, NCLS * 64);
    cvt_w4<<<256, 256>>>(fvw1, fvw2, fcw1, fcw2, ffnw);
    build_wqkv<<<768, 256>>>(Wq, Wkv, wqkvb);
    build_bias768<<<3, 256>>>(bq, bkv, b768);

    cudaMemsetAsync(numVp, 0, (size_t)OFF_V1 * sizeof(float), 0);

    // ---- fused projections: bf16 [q|k|v], stride 768 ----
    launch_gemm(v_bf, 256, wqkvb, b768, nullptr, pvb, 768, NVAR, 768, 0);
    launch_gemm(c_bf, 256, wqkvb, b768, nullptr, pcb, 768, NCLS, 768, 0);

    // ---- merged edge attention (all 4 passes) ----
    int eblocks = (int)(((size_t)4 * E * 32 + 255) / 256);
    edge_attn_all<<<eblocks, 256>>>(pvb, pcb, adj_pos, adj_neg, E,
                                    numVp, numCp, numVn, numCn,
                                    denVp, denCp, denVn, denCn);

    ln_att<<<(NVAR + 7) / 8, 256>>>(v, numVp, denVp, numVn, denVn, lavg, lavb, v1, v1b, NVAR);
    ln_att<<<(NCLS + 7) / 8, 256>>>(c, numCp, denCp, numCn, denCn, lacg, lacb, c1, c1b, NCLS);

    // FFN v
    launch_gemm(v1b, 256, fvw1b, fvb1, nullptr, hidb, 256, NVAR, 256, 1);
    launch_gemm(hidb, 256, fvw2b, fvb2, tmp, nullptr, 0, NVAR, 256, 0);
    ln_add<<<(NVAR + 7) / 8, 256>>>(v1, tmp, lfvg, lfvb, out_v, NVAR);

    // FFN c
    launch_gemm(c1b, 256, fcw1b, fcb1, nullptr, hidb, 256, NCLS, 256, 1);
    launch_gemm(hidb, 256, fcw2b, fcb2, tmp, nullptr, 0, NCLS, 256, 0);
    ln_add<<<(NCLS + 7) / 8, 256>>>(c1, tmp, lfcg, lfcb, out_c, NCLS);
}

// round 10
// speedup vs baseline: 1.0484x; 1.0484x over previous
#include <cuda_runtime.h>
#include <cuda_bf16.h>
#include <math.h>
#include <stdint.h>

#define NVAR 30000
#define NCLS 60000
#define DIM 256
#define NHEAD 8

// ---------------- scratch layout (float units) ---- R8 layout ----
#define OFF_PV     0ull            // 30000*768 fp32 (only v-part cols 512..767 written)
#define OFF_PC     23040000ull     // 60000*768 fp32
#define OFF_NUMVP  69120000ull
#define OFF_NUMVN  76800000ull
#define OFF_NUMCP  84480000ull
#define OFF_NUMCN  99840000ull
#define OFF_DENVP  115200000ull
#define OFF_DENVN  115440000ull
#define OFF_DENCP  115680000ull
#define OFF_DENCN  116160000ull
#define OFF_V1     116640000ull    // 30000*256 fp32
#define OFF_C1     124320000ull    // 60000*256 fp32
#define OFF_TMP    139680000ull    // 60000*256 fp32
#define OFF_B768   155040000ull    // 1024 floats
#define OFF_BF     155041024ull    // bf16 area
#define B_VBF   0ull               // 30000*256
#define B_CBF   7680000ull         // 60000*256
#define B_PVB   23040000ull        // 30000*512  [q|k] bf16
#define B_PCB   38400000ull        // 60000*512
#define B_V1B   69120000ull        // 30000*256
#define B_C1B   76800000ull        // 60000*256
#define B_HID   92160000ull        // 60000*256
#define B_WQKV  107520000ull       // 256*768
#define B_FFNW  107716608ull       // 4*65536
#define SCRATCH_TOTAL 209030400ull

__device__ float g_scratch[SCRATCH_TOTAL];

// ---------------- helpers ----------------
__device__ __forceinline__ void ldsm_x4(uint32_t* r, uint32_t saddr) {
    asm volatile("ldmatrix.sync.aligned.m8n8.x4.shared.b16 {%0,%1,%2,%3}, [%4];"
                 : "=r"(r[0]), "=r"(r[1]), "=r"(r[2]), "=r"(r[3]) : "r"(saddr));
}
__device__ __forceinline__ void ldsm_x4_trans(uint32_t* r, uint32_t saddr) {
    asm volatile("ldmatrix.sync.aligned.m8n8.x4.trans.shared.b16 {%0,%1,%2,%3}, [%4];"
                 : "=r"(r[0]), "=r"(r[1]), "=r"(r[2]), "=r"(r[3]) : "r"(saddr));
}
__device__ __forceinline__ void mma_bf16(float* d, const uint32_t* a, const uint32_t* b) {
    asm volatile(
        "mma.sync.aligned.m16n8k16.row.col.f32.bf16.bf16.f32 "
        "{%0,%1,%2,%3}, {%4,%5,%6,%7}, {%8,%9}, {%0,%1,%2,%3};"
        : "+f"(d[0]), "+f"(d[1]), "+f"(d[2]), "+f"(d[3])
        : "r"(a[0]), "r"(a[1]), "r"(a[2]), "r"(a[3]),
          "r"(b[0]), "r"(b[1]));
}
__device__ __forceinline__ void red_add_v4(float* addr, float4 v) {
    asm volatile("red.global.add.v4.f32 [%0], {%1,%2,%3,%4};"
                 :: "l"(addr), "f"(v.x), "f"(v.y), "f"(v.z), "f"(v.w) : "memory");
}
__device__ __forceinline__ void cp_async16(uint32_t saddr, const void* gaddr, int src_size) {
    asm volatile("cp.async.cg.shared.global [%0], [%1], 16, %2;"
                 :: "r"(saddr), "l"(gaddr), "r"(src_size));
}
#define CP_COMMIT() asm volatile("cp.async.commit_group;" ::: "memory")
#define CP_WAIT0()  asm volatile("cp.async.wait_group 0;" ::: "memory")

// ---------------- conversion kernels ----------------
__global__ void cvt_f2b4(const float* __restrict__ s, __nv_bfloat16* __restrict__ d, int n4) {
    int i = blockIdx.x * blockDim.x + threadIdx.x;
    if (i >= n4) return;
    float4 t = ((const float4*)s)[i];
    __nv_bfloat162 lo = __float22bfloat162_rn(make_float2(t.x, t.y));
    __nv_bfloat162 hi = __float22bfloat162_rn(make_float2(t.z, t.w));
    ((uint2*)d)[i] = make_uint2(*(uint32_t*)&lo, *(uint32_t*)&hi);
}
__global__ void cvt_w4(const float* __restrict__ w1, const float* __restrict__ w2,
                       const float* __restrict__ w3, const float* __restrict__ w4,
                       __nv_bfloat16* __restrict__ dst) {
    int i = blockIdx.x * blockDim.x + threadIdx.x;
    if (i >= 65536) return;
    int which = i >> 14;
    int j = i & 16383;
    const float* src = (which == 0) ? w1 : (which == 1) ? w2 : (which == 2) ? w3 : w4;
    float4 t = ((const float4*)src)[j];
    __nv_bfloat162 lo = __float22bfloat162_rn(make_float2(t.x, t.y));
    __nv_bfloat162 hi = __float22bfloat162_rn(make_float2(t.z, t.w));
    ((uint2*)(dst + (size_t)which * 65536))[j] = make_uint2(*(uint32_t*)&lo, *(uint32_t*)&hi);
}
__global__ void build_wqkv(const float* __restrict__ Wq, const float* __restrict__ Wkv,
                           __nv_bfloat16* __restrict__ dst) {
    int i = blockIdx.x * blockDim.x + threadIdx.x;
    if (i >= 256 * 768) return;
    int k = i / 768, j = i % 768;
    float val = (j < 256) ? Wq[k * 256 + j] : Wkv[k * 512 + (j - 256)];
    dst[i] = __float2bfloat16(val);
}
__global__ void build_bias768(const float* __restrict__ bq, const float* __restrict__ bkv,
                              float* __restrict__ dst) {
    int j = blockIdx.x * blockDim.x + threadIdx.x;
    if (j < 768) dst[j] = (j < 256) ? bq[j] : bkv[j - 256];
}

// ---------------- bf16 tensor-core GEMM, 128x128 tile, cp.async double-buffered ----------------
#define BM 128
#define BN 128
#define BK 32
#define ASTR 40
#define BSTR 136

__global__ __launch_bounds__(256, 2) void tgemm(
    const __nv_bfloat16* __restrict__ A, int lda,
    const __nv_bfloat16* __restrict__ W,
    const float* __restrict__ bias,
    float* __restrict__ C, int cfrom,
    __nv_bfloat16* __restrict__ Cb, int cbto, int cbs,
    int N, int M, int gelu)
{
    __shared__ __nv_bfloat16 As[2][BM * ASTR];
    __shared__ __nv_bfloat16 Ws[2][BK * BSTR];

    int tid = threadIdx.x;
    int lane = tid & 31;
    int warp = tid >> 5;
    int wm = (warp & 3) * 32;
    int wn = (warp >> 2) * 64;
    int bm = blockIdx.y * BM;
    int bn = blockIdx.x * BN;

    uint32_t as_base = (uint32_t)__cvta_generic_to_shared(&As[0][0]);
    uint32_t ws_base = (uint32_t)__cvta_generic_to_shared(&Ws[0][0]);
    const uint32_t as_sz = BM * ASTR * 2;
    const uint32_t ws_sz = BK * BSTR * 2;

    int a_row[2], a_col[2], w_row[2], w_col[2];
    uint32_t a_dst[2], w_dst[2];
    #pragma unroll
    for (int i = 0; i < 2; i++) {
        int g = tid + i * 256;
        a_row[i] = (tid * 2 + i) >> 2;
        a_col[i] = ((tid * 2 + i) & 3) * 8;
        w_row[i] = g >> 4;
        w_col[i] = (g & 15) * 8;
        a_dst[i] = as_base + (uint32_t)(a_row[i] * ASTR + a_col[i]) * 2;
        w_dst[i] = ws_base + (uint32_t)(w_row[i] * BSTR + w_col[i]) * 2;
    }

    float acc[2][8][4];
    #pragma unroll
    for (int mt = 0; mt < 2; mt++)
        #pragma unroll
        for (int nt = 0; nt < 8; nt++)
            #pragma unroll
            for (int i = 0; i < 4; i++) acc[mt][nt][i] = 0.0f;

    int a_r = lane & 15;
    int a_c = (lane >> 4) * 8;

    // ---- async-load slab 0 -> buffer 0 ----
    #pragma unroll
    for (int i = 0; i < 2; i++) {
        int gr = bm + a_row[i];
        cp_async16(a_dst[i], &A[(size_t)gr * lda + a_col[i]], (gr < N) ? 16 : 0);
        cp_async16(w_dst[i], &W[(size_t)w_row[i] * M + bn + w_col[i]], 16);
    }
    CP_COMMIT();
    CP_WAIT0();
    __syncthreads();

    for (int s = 0; s < 8; s++) {
        int cur = s & 1, nxt = cur ^ 1;
        if (s < 7) {
            int k0 = (s + 1) * BK;
            #pragma unroll
            for (int i = 0; i < 2; i++) {
                int gr = bm + a_row[i];
                cp_async16(a_dst[i] + nxt * as_sz,
                           &A[(size_t)gr * lda + k0 + a_col[i]], (gr < N) ? 16 : 0);
                cp_async16(w_dst[i] + nxt * ws_sz,
                           &W[(size_t)(k0 + w_row[i]) * M + bn + w_col[i]], 16);
            }
            CP_COMMIT();
        }

        uint32_t asb = as_base + cur * as_sz;
        uint32_t wsb = ws_base + cur * ws_sz;
        #pragma unroll
        for (int ks = 0; ks < 2; ks++) {
            int kb = ks * 16;
            uint32_t af[2][4], bf[4][4];
            #pragma unroll
            for (int mt = 0; mt < 2; mt++) {
                int row = wm + mt * 16 + a_r;
                int col = kb + a_c;
                ldsm_x4(af[mt], asb + (uint32_t)(row * ASTR + col) * 2);
            }
            #pragma unroll
            for (int p = 0; p < 4; p++) {
                int row = kb + (lane & 15);
                int col = wn + p * 16 + (lane >> 4) * 8;
                ldsm_x4_trans(bf[p], wsb + (uint32_t)(row * BSTR + col) * 2);
            }
            #pragma unroll
            for (int mt = 0; mt < 2; mt++)
                #pragma unroll
                for (int nt = 0; nt < 8; nt++)
                    mma_bf16(acc[mt][nt], af[mt], &bf[nt >> 1][(nt & 1) * 2]);
        }

        if (s < 7) {
            CP_WAIT0();
            __syncthreads();
        }
    }

    // ---- epilogue ----
    #pragma unroll
    for (int mt = 0; mt < 2; mt++) {
        int r0 = bm + wm + mt * 16 + (lane >> 2);
        #pragma unroll
        for (int nt = 0; nt < 8; nt++) {
            int cb = bn + wn + nt * 8 + (lane & 3) * 2;
            float b0 = bias[cb], b1 = bias[cb + 1];
            float2 lo = make_float2(acc[mt][nt][0] + b0, acc[mt][nt][1] + b1);
            float2 hi = make_float2(acc[mt][nt][2] + b0, acc[mt][nt][3] + b1);
            if (gelu) {
                lo.x = 0.5f * lo.x * (1.0f + erff(lo.x * 0.70710678118654752f));
                lo.y = 0.5f * lo.y * (1.0f + erff(lo.y * 0.70710678118654752f));
                hi.x = 0.5f * hi.x * (1.0f + erff(hi.x * 0.70710678118654752f));
                hi.y = 0.5f * hi.y * (1.0f + erff(hi.y * 0.70710678118654752f));
            }
            if (C && cb >= cfrom) {
                if (r0 < N)     *(float2*)&C[(size_t)r0 * M + cb] = lo;
                if (r0 + 8 < N) *(float2*)&C[(size_t)(r0 + 8) * M + cb] = hi;
            }
            if (Cb && cb < cbto) {
                __nv_bfloat162 blo = __float22bfloat162_rn(lo);
                __nv_bfloat162 bhi = __float22bfloat162_rn(hi);
                if (r0 < N)     *(__nv_bfloat162*)&Cb[(size_t)r0 * cbs + cb] = blo;
                if (r0 + 8 < N) *(__nv_bfloat162*)&Cb[(size_t)(r0 + 8) * cbs + cb] = bhi;
            }
        }
    }
}

// ---------------- edge attention: one side, BOTH polarities (2E warps) ----------------
// qSecond=1: query index is adj row1 (variables); qSecond=0: query is adj row0 (clauses).
__global__ void edge_attn2(
    const __nv_bfloat16* __restrict__ Qb,
    const __nv_bfloat16* __restrict__ KVb,
    const float* __restrict__ Vf,
    const int* __restrict__ adj_p, const int* __restrict__ adj_n,
    int E, int qSecond,
    float* __restrict__ numP, float* __restrict__ denP,
    float* __restrict__ numN, float* __restrict__ denN)
{
    int gw = (int)(((size_t)blockIdx.x * blockDim.x + threadIdx.x) >> 5);
    int lane = threadIdx.x & 31;
    if (gw >= 2 * E) return;
    int pol = gw >= E;
    int e = gw - (pol ? E : 0);
    const int* adj = pol ? adj_n : adj_p;
    int s, t;
    if (qSecond) { s = adj[E + e]; t = adj[e]; }
    else         { s = adj[e];     t = adj[E + e]; }
    float* num = pol ? numN : numP;
    float* den = pol ? denN : denP;

    uint4 qu = *(const uint4*)&Qb[(size_t)s * 512 + lane * 8];
    uint4 ku = *(const uint4*)&KVb[(size_t)t * 512 + 256 + lane * 8];
    float p = 0.0f;
    {
        const __nv_bfloat162* qp = (const __nv_bfloat162*)&qu;
        const __nv_bfloat162* kp = (const __nv_bfloat162*)&ku;
        #pragma unroll
        for (int i = 0; i < 4; i++) {
            float2 qf = __bfloat1622float2(qp[i]);
            float2 kf = __bfloat1622float2(kp[i]);
            p += qf.x * kf.x + qf.y * kf.y;
        }
    }
    p += __shfl_xor_sync(0xffffffffu, p, 1);
    p += __shfl_xor_sync(0xffffffffu, p, 2);
    float ew = __expf(p * 0.17677669529663687f);

    if ((lane & 3) == 0)
        atomicAdd(&den[(size_t)s * NHEAD + (lane >> 2)], ew);

    #pragma unroll
    for (int ch = 0; ch < 2; ch++) {
        float ec = __shfl_sync(0xffffffffu, ew, 16 * ch + ((lane >> 3) << 2));
        float4 vv = *(const float4*)&Vf[(size_t)t * 768 + 512 + ch * 128 + lane * 4];
        red_add_v4(&num[(size_t)s * 256 + ch * 128 + lane * 4],
                   make_float4(ec * vv.x, ec * vv.y, ec * vv.z, ec * vv.w));
    }
}

// ---------------- y = LN(x + num_p/den_p + num_n/den_n), dual fp32+bf16 out ----------------
__global__ void ln_att(const float* __restrict__ x,
                       const float* __restrict__ np_, const float* __restrict__ dp,
                       const float* __restrict__ nn_, const float* __restrict__ dn,
                       const float* __restrict__ g, const float* __restrict__ b,
                       float* __restrict__ y, __nv_bfloat16* __restrict__ yb, int n)
{
    int row = blockIdx.x * (blockDim.x >> 5) + (threadIdx.x >> 5);
    int lane = threadIdx.x & 31;
    if (row >= n) return;
    float vals[8];
    float s = 0.0f;
    #pragma unroll
    for (int i = 0; i < 8; i++) {
        size_t idx = (size_t)row * 256 + i * 32 + lane;
        float a = x[idx];
        float dpi = dp[(size_t)row * NHEAD + i];
        float dni = dn[(size_t)row * NHEAD + i];
        if (dpi > 0.0f) a += np_[idx] / dpi;
        if (dni > 0.0f) a += nn_[idx] / dni;
        vals[i] = a;
        s += a;
    }
    #pragma unroll
    for (int o = 16; o > 0; o >>= 1) s += __shfl_xor_sync(0xffffffffu, s, o);
    float mean = s * (1.0f / 256.0f);
    float v2 = 0.0f;
    #pragma unroll
    for (int i = 0; i < 8; i++) { float d = vals[i] - mean; v2 += d * d; }
    #pragma unroll
    for (int o = 16; o > 0; o >>= 1) v2 += __shfl_xor_sync(0xffffffffu, v2, o);
    float rstd = rsqrtf(v2 * (1.0f / 256.0f) + 1e-5f);
    #pragma unroll
    for (int i = 0; i < 8; i++) {
        int cidx = i * 32 + lane;
        float out = (vals[i] - mean) * rstd * g[cidx] + b[cidx];
        y[(size_t)row * 256 + cidx] = out;
        yb[(size_t)row * 256 + cidx] = __float2bfloat16(out);
    }
}

// ---------------- y = LN(x + a) ----------------
__global__ void ln_add(const float* __restrict__ x, const float* __restrict__ a,
                       const float* __restrict__ g, const float* __restrict__ b,
                       float* __restrict__ y, int n)
{
    int row = blockIdx.x * (blockDim.x >> 5) + (threadIdx.x >> 5);
    int lane = threadIdx.x & 31;
    if (row >= n) return;
    float vals[8];
    float s = 0.0f;
    #pragma unroll
    for (int i = 0; i < 8; i++) {
        size_t idx = (size_t)row * 256 + i * 32 + lane;
        vals[i] = x[idx] + a[idx];
        s += vals[i];
    }
    #pragma unroll
    for (int o = 16; o > 0; o >>= 1) s += __shfl_xor_sync(0xffffffffu, s, o);
    float mean = s * (1.0f / 256.0f);
    float v2 = 0.0f;
    #pragma unroll
    for (int i = 0; i < 8; i++) { float d = vals[i] - mean; v2 += d * d; }
    #pragma unroll
    for (int o = 16; o > 0; o >>= 1) v2 += __shfl_xor_sync(0xffffffffu, v2, o);
    float rstd = rsqrtf(v2 * (1.0f / 256.0f) + 1e-5f);
    #pragma unroll
    for (int i = 0; i < 8; i++) {
        int cidx = i * 32 + lane;
        y[(size_t)row * 256 + cidx] = (vals[i] - mean) * rstd * g[cidx] + b[cidx];
    }
}

static inline void launch_gemm(const __nv_bfloat16* A, int lda, const __nv_bfloat16* W,
                               const float* bias, float* C, int cfrom,
                               __nv_bfloat16* Cb, int cbto, int cbs,
                               int N, int M, int gelu) {
    dim3 grid(M / BN, (N + BM - 1) / BM);
    tgemm<<<grid, 256>>>(A, lda, W, bias, C, cfrom, Cb, cbto, cbs, N, M, gelu);
}

extern "C" void kernel_launch(void* const* d_in, const int* in_sizes, int n_in,
                              void* d_out, int out_size)
{
    const float* v       = (const float*)d_in[0];
    const float* c       = (const float*)d_in[1];
    const int*   adj_pos = (const int*)d_in[2];
    const int*   adj_neg = (const int*)d_in[3];
    const float* Wq      = (const float*)d_in[4];
    const float* bq      = (const float*)d_in[5];
    const float* Wkv     = (const float*)d_in[6];
    const float* bkv     = (const float*)d_in[7];
    const float* fvw1    = (const float*)d_in[8];
    const float* fvb1    = (const float*)d_in[9];
    const float* fvw2    = (const float*)d_in[10];
    const float* fvb2    = (const float*)d_in[11];
    const float* fcw1    = (const float*)d_in[12];
    const float* fcb1    = (const float*)d_in[13];
    const float* fcw2    = (const float*)d_in[14];
    const float* fcb2    = (const float*)d_in[15];
    const float* lavg    = (const float*)d_in[16];
    const float* lavb    = (const float*)d_in[17];
    const float* lfvg    = (const float*)d_in[18];
    const float* lfvb    = (const float*)d_in[19];
    const float* lacg    = (const float*)d_in[20];
    const float* lacb    = (const float*)d_in[21];
    const float* lfcg    = (const float*)d_in[22];
    const float* lfcb    = (const float*)d_in[23];

    int E = in_sizes[2] / 2;

    float* buf;
    cudaGetSymbolAddress((void**)&buf, g_scratch);

    float* pv    = buf + OFF_PV;
    float* pc    = buf + OFF_PC;
    float* numVp = buf + OFF_NUMVP;
    float* numVn = buf + OFF_NUMVN;
    float* numCp = buf + OFF_NUMCP;
    float* numCn = buf + OFF_NUMCN;
    float* denVp = buf + OFF_DENVP;
    float* denVn = buf + OFF_DENVN;
    float* denCp = buf + OFF_DENCP;
    float* denCn = buf + OFF_DENCN;
    float* v1    = buf + OFF_V1;
    float* c1    = buf + OFF_C1;
    float* tmp   = buf + OFF_TMP;
    float* b768  = buf + OFF_B768;

    __nv_bfloat16* bfb   = (__nv_bfloat16*)(buf + OFF_BF);
    __nv_bfloat16* v_bf  = bfb + B_VBF;
    __nv_bfloat16* c_bf  = bfb + B_CBF;
    __nv_bfloat16* pvb   = bfb + B_PVB;
    __nv_bfloat16* pcb   = bfb + B_PCB;
    __nv_bfloat16* v1b   = bfb + B_V1B;
    __nv_bfloat16* c1b   = bfb + B_C1B;
    __nv_bfloat16* hidb  = bfb + B_HID;
    __nv_bfloat16* wqkvb = bfb + B_WQKV;
    __nv_bfloat16* ffnw  = bfb + B_FFNW;
    __nv_bfloat16* fvw1b = ffnw;
    __nv_bfloat16* fvw2b = ffnw + 65536;
    __nv_bfloat16* fcw1b = ffnw + 131072;
    __nv_bfloat16* fcw2b = ffnw + 196608;

    float* out_v = (float*)d_out;
    float* out_c = out_v + (size_t)NVAR * DIM;

    // ---- conversions ----
    cvt_f2b4<<<(NVAR * 64 + 255) / 256, 256>>>(v, v_bf, NVAR * 64);
    cvt_f2b4<<<(NCLS * 64 + 255) / 256, 256>>>(c, c_bf, NCLS * 64);
    cvt_w4<<<256, 256>>>(fvw1, fvw2, fcw1, fcw2, ffnw);
    build_wqkv<<<768, 256>>>(Wq, Wkv, wqkvb);
    build_bias768<<<3, 256>>>(bq, bkv, b768);

    cudaMemsetAsync(numVp, 0, (size_t)(OFF_V1 - OFF_NUMVP) * sizeof(float), 0);

    // ---- fused projections: bf16 [q|k] + fp32 v-part ----
    launch_gemm(v_bf, 256, wqkvb, b768, pv, 512, pvb, 512, 512, NVAR, 768, 0);
    launch_gemm(c_bf, 256, wqkvb, b768, pc, 512, pcb, 512, 512, NCLS, 768, 0);

    // ---- edge attention: one launch per side, both polarities ----
    int eblocks2 = (int)(((size_t)2 * E * 32 + 255) / 256);
    edge_attn2<<<eblocks2, 256>>>(pvb, pcb, pc, adj_pos, adj_neg, E, 1,
                                  numVp, denVp, numVn, denVn);
    edge_attn2<<<eblocks2, 256>>>(pcb, pvb, pv, adj_pos, adj_neg, E, 0,
                                  numCp, denCp, numCn, denCn);

    ln_att<<<(NVAR + 7) / 8, 256>>>(v, numVp, denVp, numVn, denVn, lavg, lavb, v1, v1b, NVAR);
    ln_att<<<(NCLS + 7) / 8, 256>>>(c, numCp, denCp, numCn, denCn, lacg, lacb, c1, c1b, NCLS);

    // FFN v
    launch_gemm(v1b, 256, fvw1b, fvb1, nullptr, 1 << 30, hidb, 256, 256, NVAR, 256, 1);
    launch_gemm(hidb, 256, fvw2b, fvb2, tmp, 0, nullptr, 0, 0, NVAR, 256, 0);
    ln_add<<<(NVAR + 7) / 8, 256>>>(v1, tmp, lfvg, lfvb, out_v, NVAR);

    // FFN c
    launch_gemm(c1b, 256, fcw1b, fcb1, nullptr, 1 << 30, hidb, 256, 256, NCLS, 256, 1);
    launch_gemm(hidb, 256, fcw2b, fcb2, tmp, 0, nullptr, 0, 0, NCLS, 256, 0);
    ln_add<<<(NCLS + 7) / 8, 256>>>(c1, tmp, lfcg, lfcb, out_c, NCLS);
}

// round 11
// speedup vs baseline: 1.0865x; 1.0364x over previous
#include <cuda_runtime.h>
#include <cuda_bf16.h>
#include <math.h>
#include <stdint.h>

#define NVAR 30000
#define NCLS 60000
#define NTOT 90000
#define NVP  30080          // v rows padded to multiple of 128 for merged FFN
#define NTOTP 90080
#define DIM 256
#define NHEAD 8

// ---------------- scratch layout (float units) ----------------
#define OFF_NUMVP  0ull             // 30000*256
#define OFF_NUMVN  7680000ull
#define OFF_NUMCP  15360000ull      // 60000*256
#define OFF_NUMCN  30720000ull
#define OFF_DENVP  46080000ull
#define OFF_DENVN  46320000ull
#define OFF_DENCP  46560000ull
#define OFF_DENCN  47040000ull
#define OFF_PVF    47520000ull      // 90000*256 fp32 v-part (compact)
#define OFF_V1M    70560000ull      // 90080*256 fp32
#define OFF_TMPM   93620480ull      // 90080*256 fp32
#define OFF_B768   116680960ull     // 1024
#define OFF_BF     116682000ull     // bf16 area (bf16-element offsets below)
#define B_XB    0ull                // 90000*256  inputs bf16 (v then c)
#define B_PB    23040000ull         // 90000*512  [q|k] bf16
#define B_X1B   69120000ull         // 90080*256  post-att LN bf16
#define B_HID   92180480ull         // 90080*256
#define B_WQKV  115240960ull        // 256*768
#define B_FFNW  115437568ull        // 4*65536
// bf16 total 115,699,712 -> 57,849,856 floats
#define SCRATCH_TOTAL 174531856ull

__device__ float g_scratch[SCRATCH_TOTAL];

// ---------------- helpers ----------------
__device__ __forceinline__ void ldsm_x4(uint32_t* r, uint32_t saddr) {
    asm volatile("ldmatrix.sync.aligned.m8n8.x4.shared.b16 {%0,%1,%2,%3}, [%4];"
                 : "=r"(r[0]), "=r"(r[1]), "=r"(r[2]), "=r"(r[3]) : "r"(saddr));
}
__device__ __forceinline__ void ldsm_x4_trans(uint32_t* r, uint32_t saddr) {
    asm volatile("ldmatrix.sync.aligned.m8n8.x4.trans.shared.b16 {%0,%1,%2,%3}, [%4];"
                 : "=r"(r[0]), "=r"(r[1]), "=r"(r[2]), "=r"(r[3]) : "r"(saddr));
}
__device__ __forceinline__ void mma_bf16(float* d, const uint32_t* a, const uint32_t* b) {
    asm volatile(
        "mma.sync.aligned.m16n8k16.row.col.f32.bf16.bf16.f32 "
        "{%0,%1,%2,%3}, {%4,%5,%6,%7}, {%8,%9}, {%0,%1,%2,%3};"
        : "+f"(d[0]), "+f"(d[1]), "+f"(d[2]), "+f"(d[3])
        : "r"(a[0]), "r"(a[1]), "r"(a[2]), "r"(a[3]),
          "r"(b[0]), "r"(b[1]));
}
__device__ __forceinline__ void red_add_v4(float* addr, float4 v) {
    asm volatile("red.global.add.v4.f32 [%0], {%1,%2,%3,%4};"
                 :: "l"(addr), "f"(v.x), "f"(v.y), "f"(v.z), "f"(v.w) : "memory");
}
__device__ __forceinline__ void cp_async16(uint32_t saddr, const void* gaddr, int src_size) {
    asm volatile("cp.async.cg.shared.global [%0], [%1], 16, %2;"
                 :: "r"(saddr), "l"(gaddr), "r"(src_size));
}
#define CP_COMMIT() asm volatile("cp.async.commit_group;" ::: "memory")
#define CP_WAIT0()  asm volatile("cp.async.wait_group 0;" ::: "memory")

// ---------------- conversion kernels ----------------
__global__ void cvt_x(const float* __restrict__ v, const float* __restrict__ c,
                      __nv_bfloat16* __restrict__ d) {
    int i = blockIdx.x * blockDim.x + threadIdx.x;   // float4 index
    if (i >= NTOT * 64) return;
    const float* src = (i < NVAR * 64) ? v : c - (size_t)NVAR * 256;
    float4 t = ((const float4*)src)[i];
    __nv_bfloat162 lo = __float22bfloat162_rn(make_float2(t.x, t.y));
    __nv_bfloat162 hi = __float22bfloat162_rn(make_float2(t.z, t.w));
    ((uint2*)d)[i] = make_uint2(*(uint32_t*)&lo, *(uint32_t*)&hi);
}
__global__ void cvt_w4(const float* __restrict__ w1, const float* __restrict__ w2,
                       const float* __restrict__ w3, const float* __restrict__ w4,
                       __nv_bfloat16* __restrict__ dst) {
    int i = blockIdx.x * blockDim.x + threadIdx.x;
    if (i >= 65536) return;
    int which = i >> 14;
    int j = i & 16383;
    const float* src = (which == 0) ? w1 : (which == 1) ? w2 : (which == 2) ? w3 : w4;
    float4 t = ((const float4*)src)[j];
    __nv_bfloat162 lo = __float22bfloat162_rn(make_float2(t.x, t.y));
    __nv_bfloat162 hi = __float22bfloat162_rn(make_float2(t.z, t.w));
    ((uint2*)(dst + (size_t)which * 65536))[j] = make_uint2(*(uint32_t*)&lo, *(uint32_t*)&hi);
}
__global__ void build_wqkv(const float* __restrict__ Wq, const float* __restrict__ Wkv,
                           __nv_bfloat16* __restrict__ dst) {
    int i = blockIdx.x * blockDim.x + threadIdx.x;
    if (i >= 256 * 768) return;
    int k = i / 768, j = i % 768;
    float val = (j < 256) ? Wq[k * 256 + j] : Wkv[k * 512 + (j - 256)];
    dst[i] = __float2bfloat16(val);
}
__global__ void build_bias768(const float* __restrict__ bq, const float* __restrict__ bkv,
                              float* __restrict__ dst) {
    int j = blockIdx.x * blockDim.x + threadIdx.x;
    if (j < 768) dst[j] = (j < 256) ? bq[j] : bkv[j - 256];
}

// ---------------- bf16 tensor-core GEMM, 128x128 tile, cp.async, split weights ----------------
#define BM 128
#define BN 128
#define BK 32
#define ASTR 40
#define BSTR 136

__global__ __launch_bounds__(256, 2) void tgemm(
    const __nv_bfloat16* __restrict__ A, int lda,
    const __nv_bfloat16* __restrict__ W1, const __nv_bfloat16* __restrict__ W2, int nsplit,
    const float* __restrict__ bias1, const float* __restrict__ bias2,
    float* __restrict__ C, int cfrom, int cs,
    __nv_bfloat16* __restrict__ Cb, int cbto, int cbs,
    int N, int M, int gelu)
{
    __shared__ __nv_bfloat16 As[2][BM * ASTR];
    __shared__ __nv_bfloat16 Ws[2][BK * BSTR];

    int tid = threadIdx.x;
    int lane = tid & 31;
    int warp = tid >> 5;
    int wm = (warp & 3) * 32;
    int wn = (warp >> 2) * 64;
    int bm = blockIdx.y * BM;
    int bn = blockIdx.x * BN;

    bool second = (W2 != nullptr) && (bm >= nsplit);
    const __nv_bfloat16* W = second ? W2 : W1;
    const float* bias = second ? bias2 : bias1;

    uint32_t as_base = (uint32_t)__cvta_generic_to_shared(&As[0][0]);
    uint32_t ws_base = (uint32_t)__cvta_generic_to_shared(&Ws[0][0]);
    const uint32_t as_sz = BM * ASTR * 2;
    const uint32_t ws_sz = BK * BSTR * 2;

    int a_row[2], a_col[2], w_row[2], w_col[2];
    uint32_t a_dst[2], w_dst[2];
    #pragma unroll
    for (int i = 0; i < 2; i++) {
        int g = tid + i * 256;
        a_row[i] = (tid * 2 + i) >> 2;
        a_col[i] = ((tid * 2 + i) & 3) * 8;
        w_row[i] = g >> 4;
        w_col[i] = (g & 15) * 8;
        a_dst[i] = as_base + (uint32_t)(a_row[i] * ASTR + a_col[i]) * 2;
        w_dst[i] = ws_base + (uint32_t)(w_row[i] * BSTR + w_col[i]) * 2;
    }

    float acc[2][8][4];
    #pragma unroll
    for (int mt = 0; mt < 2; mt++)
        #pragma unroll
        for (int nt = 0; nt < 8; nt++)
            #pragma unroll
            for (int i = 0; i < 4; i++) acc[mt][nt][i] = 0.0f;

    int a_r = lane & 15;
    int a_c = (lane >> 4) * 8;

    #pragma unroll
    for (int i = 0; i < 2; i++) {
        int gr = bm + a_row[i];
        cp_async16(a_dst[i], &A[(size_t)gr * lda + a_col[i]], (gr < N) ? 16 : 0);
        cp_async16(w_dst[i], &W[(size_t)w_row[i] * M + bn + w_col[i]], 16);
    }
    CP_COMMIT();
    CP_WAIT0();
    __syncthreads();

    for (int s = 0; s < 8; s++) {
        int cur = s & 1, nxt = cur ^ 1;
        if (s < 7) {
            int k0 = (s + 1) * BK;
            #pragma unroll
            for (int i = 0; i < 2; i++) {
                int gr = bm + a_row[i];
                cp_async16(a_dst[i] + nxt * as_sz,
                           &A[(size_t)gr * lda + k0 + a_col[i]], (gr < N) ? 16 : 0);
                cp_async16(w_dst[i] + nxt * ws_sz,
                           &W[(size_t)(k0 + w_row[i]) * M + bn + w_col[i]], 16);
            }
            CP_COMMIT();
        }

        uint32_t asb = as_base + cur * as_sz;
        uint32_t wsb = ws_base + cur * ws_sz;
        #pragma unroll
        for (int ks = 0; ks < 2; ks++) {
            int kb = ks * 16;
            uint32_t af[2][4], bf[4][4];
            #pragma unroll
            for (int mt = 0; mt < 2; mt++) {
                int row = wm + mt * 16 + a_r;
                int col = kb + a_c;
                ldsm_x4(af[mt], asb + (uint32_t)(row * ASTR + col) * 2);
            }
            #pragma unroll
            for (int p = 0; p < 4; p++) {
                int row = kb + (lane & 15);
                int col = wn + p * 16 + (lane >> 4) * 8;
                ldsm_x4_trans(bf[p], wsb + (uint32_t)(row * BSTR + col) * 2);
            }
            #pragma unroll
            for (int mt = 0; mt < 2; mt++)
                #pragma unroll
                for (int nt = 0; nt < 8; nt++)
                    mma_bf16(acc[mt][nt], af[mt], &bf[nt >> 1][(nt & 1) * 2]);
        }

        if (s < 7) {
            CP_WAIT0();
            __syncthreads();
        }
    }

    #pragma unroll
    for (int mt = 0; mt < 2; mt++) {
        int r0 = bm + wm + mt * 16 + (lane >> 2);
        #pragma unroll
        for (int nt = 0; nt < 8; nt++) {
            int cb = bn + wn + nt * 8 + (lane & 3) * 2;
            float b0 = bias[cb], b1 = bias[cb + 1];
            float2 lo = make_float2(acc[mt][nt][0] + b0, acc[mt][nt][1] + b1);
            float2 hi = make_float2(acc[mt][nt][2] + b0, acc[mt][nt][3] + b1);
            if (gelu) {
                lo.x = 0.5f * lo.x * (1.0f + erff(lo.x * 0.70710678118654752f));
                lo.y = 0.5f * lo.y * (1.0f + erff(lo.y * 0.70710678118654752f));
                hi.x = 0.5f * hi.x * (1.0f + erff(hi.x * 0.70710678118654752f));
                hi.y = 0.5f * hi.y * (1.0f + erff(hi.y * 0.70710678118654752f));
            }
            if (C && cb >= cfrom) {
                if (r0 < N)     *(float2*)&C[(size_t)r0 * cs + cb - cfrom] = lo;
                if (r0 + 8 < N) *(float2*)&C[(size_t)(r0 + 8) * cs + cb - cfrom] = hi;
            }
            if (Cb && cb < cbto) {
                __nv_bfloat162 blo = __float22bfloat162_rn(lo);
                __nv_bfloat162 bhi = __float22bfloat162_rn(hi);
                if (r0 < N)     *(__nv_bfloat162*)&Cb[(size_t)r0 * cbs + cb] = blo;
                if (r0 + 8 < N) *(__nv_bfloat162*)&Cb[(size_t)(r0 + 8) * cbs + cb] = bhi;
            }
        }
    }
}

// ---------------- edge attention: one side, BOTH polarities ----------------
__global__ void edge_attn2(
    const __nv_bfloat16* __restrict__ Qb,
    const __nv_bfloat16* __restrict__ KVb,
    const float* __restrict__ Vf,          // compact stride 256
    const int* __restrict__ adj_p, const int* __restrict__ adj_n,
    int E, int qSecond,
    float* __restrict__ numP, float* __restrict__ denP,
    float* __restrict__ numN, float* __restrict__ denN)
{
    int gw = (int)(((size_t)blockIdx.x * blockDim.x + threadIdx.x) >> 5);
    int lane = threadIdx.x & 31;
    if (gw >= 2 * E) return;
    int pol = gw >= E;
    int e = gw - (pol ? E : 0);
    const int* adj = pol ? adj_n : adj_p;
    int s, t;
    if (qSecond) { s = adj[E + e]; t = adj[e]; }
    else         { s = adj[e];     t = adj[E + e]; }
    float* num = pol ? numN : numP;
    float* den = pol ? denN : denP;

    uint4 qu = *(const uint4*)&Qb[(size_t)s * 512 + lane * 8];
    uint4 ku = *(const uint4*)&KVb[(size_t)t * 512 + 256 + lane * 8];
    float p = 0.0f;
    {
        const __nv_bfloat162* qp = (const __nv_bfloat162*)&qu;
        const __nv_bfloat162* kp = (const __nv_bfloat162*)&ku;
        #pragma unroll
        for (int i = 0; i < 4; i++) {
            float2 qf = __bfloat1622float2(qp[i]);
            float2 kf = __bfloat1622float2(kp[i]);
            p += qf.x * kf.x + qf.y * kf.y;
        }
    }
    p += __shfl_xor_sync(0xffffffffu, p, 1);
    p += __shfl_xor_sync(0xffffffffu, p, 2);
    float ew = __expf(p * 0.17677669529663687f);

    if ((lane & 3) == 0)
        atomicAdd(&den[(size_t)s * NHEAD + (lane >> 2)], ew);

    #pragma unroll
    for (int ch = 0; ch < 2; ch++) {
        float ec = __shfl_sync(0xffffffffu, ew, 16 * ch + ((lane >> 3) << 2));
        float4 vv = *(const float4*)&Vf[(size_t)t * 256 + ch * 128 + lane * 4];
        red_add_v4(&num[(size_t)s * 256 + ch * 128 + lane * 4],
                   make_float4(ec * vv.x, ec * vv.y, ec * vv.z, ec * vv.w));
    }
}

// ---------------- merged attention LN: v rows then c rows ----------------
__global__ void ln_att_m(const float* __restrict__ xv, const float* __restrict__ xc,
                         const float* __restrict__ nVp, const float* __restrict__ dVp,
                         const float* __restrict__ nVn, const float* __restrict__ dVn,
                         const float* __restrict__ nCp, const float* __restrict__ dCp,
                         const float* __restrict__ nCn, const float* __restrict__ dCn,
                         const float* __restrict__ gv, const float* __restrict__ bv,
                         const float* __restrict__ gc, const float* __restrict__ bc,
                         float* __restrict__ y, __nv_bfloat16* __restrict__ yb)
{
    int gr = blockIdx.x * (blockDim.x >> 5) + (threadIdx.x >> 5);
    int lane = threadIdx.x & 31;
    if (gr >= NTOT) return;
    bool isv = gr < NVAR;
    int node = isv ? gr : gr - NVAR;
    const float* x  = isv ? xv : xc;
    const float* np_ = isv ? nVp : nCp;
    const float* dp  = isv ? dVp : dCp;
    const float* nn_ = isv ? nVn : nCn;
    const float* dn  = isv ? dVn : dCn;
    const float* g = isv ? gv : gc;
    const float* b = isv ? bv : bc;
    size_t orow = isv ? (size_t)gr : (size_t)NVP + node;

    float vals[8];
    float s = 0.0f;
    #pragma unroll
    for (int i = 0; i < 8; i++) {
        size_t idx = (size_t)node * 256 + i * 32 + lane;
        float a = x[idx];
        float dpi = dp[(size_t)node * NHEAD + i];
        float dni = dn[(size_t)node * NHEAD + i];
        if (dpi > 0.0f) a += np_[idx] / dpi;
        if (dni > 0.0f) a += nn_[idx] / dni;
        vals[i] = a;
        s += a;
    }
    #pragma unroll
    for (int o = 16; o > 0; o >>= 1) s += __shfl_xor_sync(0xffffffffu, s, o);
    float mean = s * (1.0f / 256.0f);
    float v2 = 0.0f;
    #pragma unroll
    for (int i = 0; i < 8; i++) { float d = vals[i] - mean; v2 += d * d; }
    #pragma unroll
    for (int o = 16; o > 0; o >>= 1) v2 += __shfl_xor_sync(0xffffffffu, v2, o);
    float rstd = rsqrtf(v2 * (1.0f / 256.0f) + 1e-5f);
    #pragma unroll
    for (int i = 0; i < 8; i++) {
        int cidx = i * 32 + lane;
        float out = (vals[i] - mean) * rstd * g[cidx] + b[cidx];
        y[orow * 256 + cidx] = out;
        yb[orow * 256 + cidx] = __float2bfloat16(out);
    }
}

// ---------------- merged final LN: y = LN(x + a) ----------------
__global__ void ln_add_m(const float* __restrict__ x, const float* __restrict__ a,
                         const float* __restrict__ gv, const float* __restrict__ bv,
                         const float* __restrict__ gc, const float* __restrict__ bc,
                         float* __restrict__ out_v, float* __restrict__ out_c)
{
    int gr = blockIdx.x * (blockDim.x >> 5) + (threadIdx.x >> 5);
    int lane = threadIdx.x & 31;
    if (gr >= NTOT) return;
    bool isv = gr < NVAR;
    int node = isv ? gr : gr - NVAR;
    size_t brow = isv ? (size_t)gr : (size_t)NVP + node;
    const float* g = isv ? gv : gc;
    const float* b = isv ? bv : bc;
    float* y = isv ? out_v : out_c;

    float vals[8];
    float s = 0.0f;
    #pragma unroll
    for (int i = 0; i < 8; i++) {
        size_t idx = brow * 256 + i * 32 + lane;
        vals[i] = x[idx] + a[idx];
        s += vals[i];
    }
    #pragma unroll
    for (int o = 16; o > 0; o >>= 1) s += __shfl_xor_sync(0xffffffffu, s, o);
    float mean = s * (1.0f / 256.0f);
    float v2 = 0.0f;
    #pragma unroll
    for (int i = 0; i < 8; i++) { float d = vals[i] - mean; v2 += d * d; }
    #pragma unroll
    for (int o = 16; o > 0; o >>= 1) v2 += __shfl_xor_sync(0xffffffffu, v2, o);
    float rstd = rsqrtf(v2 * (1.0f / 256.0f) + 1e-5f);
    #pragma unroll
    for (int i = 0; i < 8; i++) {
        int cidx = i * 32 + lane;
        y[(size_t)node * 256 + cidx] = (vals[i] - mean) * rstd * g[cidx] + b[cidx];
    }
}

extern "C" void kernel_launch(void* const* d_in, const int* in_sizes, int n_in,
                              void* d_out, int out_size)
{
    const float* v       = (const float*)d_in[0];
    const float* c       = (const float*)d_in[1];
    const int*   adj_pos = (const int*)d_in[2];
    const int*   adj_neg = (const int*)d_in[3];
    const float* Wq      = (const float*)d_in[4];
    const float* bq      = (const float*)d_in[5];
    const float* Wkv     = (const float*)d_in[6];
    const float* bkv     = (const float*)d_in[7];
    const float* fvw1    = (const float*)d_in[8];
    const float* fvb1    = (const float*)d_in[9];
    const float* fvw2    = (const float*)d_in[10];
    const float* fvb2    = (const float*)d_in[11];
    const float* fcw1    = (const float*)d_in[12];
    const float* fcb1    = (const float*)d_in[13];
    const float* fcw2    = (const float*)d_in[14];
    const float* fcb2    = (const float*)d_in[15];
    const float* lavg    = (const float*)d_in[16];
    const float* lavb    = (const float*)d_in[17];
    const float* lfvg    = (const float*)d_in[18];
    const float* lfvb    = (const float*)d_in[19];
    const float* lacg    = (const float*)d_in[20];
    const float* lacb    = (const float*)d_in[21];
    const float* lfcg    = (const float*)d_in[22];
    const float* lfcb    = (const float*)d_in[23];

    int E = in_sizes[2] / 2;

    float* buf;
    cudaGetSymbolAddress((void**)&buf, g_scratch);

    float* numVp = buf + OFF_NUMVP;
    float* numVn = buf + OFF_NUMVN;
    float* numCp = buf + OFF_NUMCP;
    float* numCn = buf + OFF_NUMCN;
    float* denVp = buf + OFF_DENVP;
    float* denVn = buf + OFF_DENVN;
    float* denCp = buf + OFF_DENCP;
    float* denCn = buf + OFF_DENCN;
    float* pvf   = buf + OFF_PVF;    // fp32 v-part, 90000 x 256 (v nodes then c nodes)
    float* v1m   = buf + OFF_V1M;    // 90080 x 256
    float* tmpm  = buf + OFF_TMPM;
    float* b768  = buf + OFF_B768;

    __nv_bfloat16* bfb   = (__nv_bfloat16*)(buf + OFF_BF);
    __nv_bfloat16* xb    = bfb + B_XB;
    __nv_bfloat16* pb    = bfb + B_PB;     // [q|k] 90000 x 512
    __nv_bfloat16* x1b   = bfb + B_X1B;    // 90080 x 256
    __nv_bfloat16* hidb  = bfb + B_HID;
    __nv_bfloat16* wqkvb = bfb + B_WQKV;
    __nv_bfloat16* ffnw  = bfb + B_FFNW;
    __nv_bfloat16* fvw1b = ffnw;
    __nv_bfloat16* fvw2b = ffnw + 65536;
    __nv_bfloat16* fcw1b = ffnw + 131072;
    __nv_bfloat16* fcw2b = ffnw + 196608;

    __nv_bfloat16* pvb = pb;                       // v nodes
    __nv_bfloat16* pcb = pb + (size_t)NVAR * 512;  // c nodes
    float* vfv = pvf;                              // v-part of v nodes
    float* vfc = pvf + (size_t)NVAR * 256;         // v-part of c nodes

    float* out_v = (float*)d_out;
    float* out_c = out_v + (size_t)NVAR * DIM;

    // ---- conversions ----
    cvt_x<<<(NTOT * 64 + 255) / 256, 256>>>(v, c, xb);
    cvt_w4<<<256, 256>>>(fvw1, fvw2, fcw1, fcw2, ffnw);
    build_wqkv<<<768, 256>>>(Wq, Wkv, wqkvb);
    build_bias768<<<3, 256>>>(bq, bkv, b768);

    cudaMemsetAsync(numVp, 0, (size_t)OFF_PVF * sizeof(float), 0);

    // ---- merged projection: 90000 x 768, bf16 [q|k] + compact fp32 v ----
    {
        dim3 grid(768 / BN, (NTOT + BM - 1) / BM);
        tgemm<<<grid, 256>>>(xb, 256, wqkvb, nullptr, 0, b768, b768,
                             pvf, 512, 256, pb, 512, 512, NTOT, 768, 0);
    }

    // ---- edge attention: one launch per side, both polarities ----
    int eblocks2 = (int)(((size_t)2 * E * 32 + 255) / 256);
    edge_attn2<<<eblocks2, 256>>>(pvb, pcb, vfc, adj_pos, adj_neg, E, 1,
                                  numVp, denVp, numVn, denVn);
    edge_attn2<<<eblocks2, 256>>>(pcb, pvb, vfv, adj_pos, adj_neg, E, 0,
                                  numCp, denCp, numCn, denCn);

    // ---- merged attention LN ----
    ln_att_m<<<(NTOT + 7) / 8, 256>>>(v, c,
                                      numVp, denVp, numVn, denVn,
                                      numCp, denCp, numCn, denCn,
                                      lavg, lavb, lacg, lacb, v1m, x1b);

    // ---- merged FFN (split weights at row NVP) ----
    {
        dim3 grid(256 / BN, (NTOTP + BM - 1) / BM);
        tgemm<<<grid, 256>>>(x1b, 256, fvw1b, fcw1b, NVP, fvb1, fcb1,
                             nullptr, 1 << 30, 0, hidb, 256, 256, NTOTP, 256, 1);
        tgemm<<<grid, 256>>>(hidb, 256, fvw2b, fcw2b, NVP, fvb2, fcb2,
                             tmpm, 0, 256, nullptr, 0, 0, NTOTP, 256, 0);
    }

    // ---- merged final LN ----
    ln_add_m<<<(NTOT + 7) / 8, 256>>>(v1m, tmpm, lfvg, lfvb, lfcg, lfcb, out_v, out_c);
}